// round 4
// baseline (speedup 1.0000x reference)
#include <cuda_runtime.h>
#include <cuda_bf16.h>
#include <math.h>

// Problem constants
#define BB 2
#define TT 2048
#define CC 1024
#define HH 16
#define HD 64
#define M_TOT (BB*TT)        // 4096
#define N_QKV (3*CC)         // 3072

// Scratch (device globals: allocation-free)
__device__ float g_q[BB*HH*TT*HD];   // [B,H,T,64]
__device__ float g_k[BB*HH*TT*HD];
__device__ float g_v[BB*HH*TT*HD];
__device__ float g_y[BB*TT*CC];      // [B,T,C]

// ---------------------------------------------------------------------------
// GEMM: C[m,n] = sum_k A[m,k]*B[n,k] + bias[n]   (A row-major [M,K], B row-major [N,K])
// BM=BN=128, BK=8, 256 threads, 8x8 per-thread tile.
// MODE 1: QKV epilogue (scatter into g_q/g_k/g_v, [B,H,T,64] layout)
// MODE 2: proj (A := g_y, plain store to C)
// ---------------------------------------------------------------------------
#define BM 128
#define BN 128
#define BK 8

template<int MODE>
__global__ __launch_bounds__(256) void gemm_kernel(
    const float* __restrict__ A, const float* __restrict__ B,
    const float* __restrict__ bias, float* __restrict__ C,
    int M, int N, int K)
{
    __shared__ float As[BK][BM];
    __shared__ float Bs[BK][BN];

    const float* Ap = (MODE == 2) ? (const float*)g_y : A;

    int tid  = threadIdx.x;
    int m0   = blockIdx.y * BM;
    int n0   = blockIdx.x * BN;
    int tRow = tid >> 4;        // 0..15
    int tCol = tid & 15;        // 0..15

    // load mapping: each thread loads one float4 of A and one of B per k-tile
    int lr = tid >> 1;          // 0..127
    int lk = (tid & 1) << 2;    // 0 or 4

    const float* Ag = Ap + (size_t)(m0 + lr) * K + lk;
    const float* Bg = B  + (size_t)(n0 + lr) * K + lk;

    float acc[8][8];
#pragma unroll
    for (int i = 0; i < 8; i++)
#pragma unroll
        for (int j = 0; j < 8; j++) acc[i][j] = 0.f;

    for (int k0 = 0; k0 < K; k0 += BK) {
        float4 av = *reinterpret_cast<const float4*>(Ag + k0);
        float4 bv = *reinterpret_cast<const float4*>(Bg + k0);
        As[lk+0][lr] = av.x; As[lk+1][lr] = av.y; As[lk+2][lr] = av.z; As[lk+3][lr] = av.w;
        Bs[lk+0][lr] = bv.x; Bs[lk+1][lr] = bv.y; Bs[lk+2][lr] = bv.z; Bs[lk+3][lr] = bv.w;
        __syncthreads();

#pragma unroll
        for (int k = 0; k < BK; k++) {
            float a[8], b[8];
            *reinterpret_cast<float4*>(&a[0]) = *reinterpret_cast<const float4*>(&As[k][tRow*8]);
            *reinterpret_cast<float4*>(&a[4]) = *reinterpret_cast<const float4*>(&As[k][tRow*8+4]);
            *reinterpret_cast<float4*>(&b[0]) = *reinterpret_cast<const float4*>(&Bs[k][tCol*8]);
            *reinterpret_cast<float4*>(&b[4]) = *reinterpret_cast<const float4*>(&Bs[k][tCol*8+4]);
#pragma unroll
            for (int i = 0; i < 8; i++)
#pragma unroll
                for (int j = 0; j < 8; j++)
                    acc[i][j] += a[i] * b[j];
        }
        __syncthreads();
    }

    if (MODE == 1) {
        // scatter into q/k/v [B,H,T,64]
#pragma unroll
        for (int i = 0; i < 8; i++) {
            int m  = m0 + tRow*8 + i;
            int bb = m >> 11;        // /2048
            int t  = m & 2047;
#pragma unroll
            for (int j = 0; j < 8; j++) {
                int n = n0 + tCol*8 + j;
                float v = acc[i][j] + bias[n];
                int which = n >> 10;       // 0=q 1=k 2=v
                int c = n & 1023;
                int h = c >> 6;
                int d = c & 63;
                size_t idx = ((((size_t)bb*HH + h)*TT) + t)*HD + d;
                if (which == 0)      g_q[idx] = v;
                else if (which == 1) g_k[idx] = v;
                else                 g_v[idx] = v;
            }
        }
    } else {
#pragma unroll
        for (int i = 0; i < 8; i++) {
            int m = m0 + tRow*8 + i;
            float* Crow = C + (size_t)m * N + n0 + tCol*8;
#pragma unroll
            for (int j = 0; j < 8; j++)
                Crow[j] = acc[i][j] + bias[n0 + tCol*8 + j];
        }
    }
}

// ---------------------------------------------------------------------------
// Flash attention (fp32, causal). Block = (64-row Q tile, one (b,h)).
// 64 threads, one thread per Q row. Q and O in registers, K/V/S in smem.
// ---------------------------------------------------------------------------
__global__ __launch_bounds__(64) void attn_kernel()
{
    __shared__ float Ks[64*64];
    __shared__ float Vs[64*64];
    __shared__ float Ss[64*64];   // Ss[j*64 + r] : thread-private column, no sync needed

    int r  = threadIdx.x;         // q row within tile
    int bh = blockIdx.y;          // 0..31  (b*16 + h)
    int q0 = blockIdx.x * 64;

    size_t headoff = (size_t)bh * (TT*HD);

    // Q row -> registers
    const float4* Qg = reinterpret_cast<const float4*>(g_q + headoff + (size_t)(q0 + r)*HD);
    float q[64], o[64];
#pragma unroll
    for (int i = 0; i < 16; i++) {
        float4 t4 = Qg[i];
        q[4*i+0] = t4.x; q[4*i+1] = t4.y; q[4*i+2] = t4.z; q[4*i+3] = t4.w;
    }
#pragma unroll
    for (int i = 0; i < 64; i++) o[i] = 0.f;

    float mprev = -INFINITY, l = 0.f;
    int ntiles = blockIdx.x + 1;               // causal: only tiles up to the diagonal

    for (int kt = 0; kt < ntiles; kt++) {
        // stage K/V tiles, fully coalesced linear copy
        const float4* Kg = reinterpret_cast<const float4*>(g_k + headoff + (size_t)kt*64*HD);
        const float4* Vg = reinterpret_cast<const float4*>(g_v + headoff + (size_t)kt*64*HD);
        float4* Ks4 = reinterpret_cast<float4*>(Ks);
        float4* Vs4 = reinterpret_cast<float4*>(Vs);
        for (int i = r; i < 1024; i += 64) { Ks4[i] = Kg[i]; Vs4[i] = Vg[i]; }
        __syncthreads();

        int lim = q0 + r - kt*64;              // valid: j <= lim   (always >= 0 here)
        float mt = mprev;

        // S = scale * Q K^T  (per thread: its own row vs all 64 k-cols)
        for (int j = 0; j < 64; j++) {
            const float4* kr = reinterpret_cast<const float4*>(Ks + j*64);
            float s0 = 0.f, s1 = 0.f, s2 = 0.f, s3 = 0.f;   // 4 chains: hide FFMA latency
#pragma unroll
            for (int i = 0; i < 16; i++) {
                float4 kv = kr[i];
                s0 += q[4*i+0]*kv.x;
                s1 += q[4*i+1]*kv.y;
                s2 += q[4*i+2]*kv.z;
                s3 += q[4*i+3]*kv.w;
            }
            float s = ((s0 + s1) + (s2 + s3)) * 0.125f;
            s = (j <= lim) ? s : -INFINITY;
            mt = fmaxf(mt, s);
            Ss[j*64 + r] = s;                  // same thread writes & reads this slot
        }

        // online softmax rescale
        float alpha = __expf(mprev - mt);      // first tile: exp(-inf)=0
        l *= alpha;
#pragma unroll
        for (int i = 0; i < 64; i++) o[i] *= alpha;

        // P·V accumulate
        for (int j = 0; j < 64; j++) {
            float p = __expf(Ss[j*64 + r] - mt);
            l += p;
            const float4* vr = reinterpret_cast<const float4*>(Vs + j*64);
#pragma unroll
            for (int i = 0; i < 16; i++) {
                float4 vv = vr[i];
                o[4*i+0] += p*vv.x;
                o[4*i+1] += p*vv.y;
                o[4*i+2] += p*vv.z;
                o[4*i+3] += p*vv.w;
            }
        }
        mprev = mt;
        __syncthreads();                       // before next tile overwrites Ks/Vs
    }

    float inv = 1.f / l;
    int b = bh >> 4, h = bh & 15;
    // write into [B,T,C] layout for the projection GEMM
    float* dst = g_y + (((size_t)b*TT + q0 + r)*CC) + h*HD;
    float4* dst4 = reinterpret_cast<float4*>(dst);
#pragma unroll
    for (int i = 0; i < 16; i++) {
        float4 ov;
        ov.x = o[4*i+0]*inv; ov.y = o[4*i+1]*inv;
        ov.z = o[4*i+2]*inv; ov.w = o[4*i+3]*inv;
        dst4[i] = ov;
    }
}

// ---------------------------------------------------------------------------
extern "C" void kernel_launch(void* const* d_in, const int* in_sizes, int n_in,
                              void* d_out, int out_size)
{
    const float* x      = (const float*)d_in[0];   // [B,T,C]
    const float* W_attn = (const float*)d_in[1];   // [3C,C]
    const float* b_attn = (const float*)d_in[2];   // [3C]
    const float* W_proj = (const float*)d_in[3];   // [C,C]
    const float* b_proj = (const float*)d_in[4];   // [C]
    float* out = (float*)d_out;                    // [B,T,C]

    // 1) QKV projection + head-split scatter
    gemm_kernel<1><<<dim3(N_QKV/BN, M_TOT/BM), 256>>>(x, W_attn, b_attn, nullptr,
                                                      M_TOT, N_QKV, CC);
    // 2) causal flash attention
    attn_kernel<<<dim3(TT/64, BB*HH), 64>>>();

    // 3) output projection
    gemm_kernel<2><<<dim3(CC/BN, M_TOT/BM), 256>>>(nullptr, W_proj, b_proj, out,
                                                   M_TOT, CC, CC);
}

// round 7
// speedup vs baseline: 1.4249x; 1.4249x over previous
#include <cuda_runtime.h>
#include <cuda_bf16.h>
#include <math.h>
#include <stdint.h>

// Problem constants
#define BB 2
#define TT 2048
#define CC 1024
#define HH 16
#define HD 64
#define M_TOT (BB*TT)        // 4096
#define N_QKV (3*CC)         // 3072

// Scratch (device globals: allocation-free)
__device__ float g_q[BB*HH*TT*HD];   // [B,H,T,64]
__device__ float g_k[BB*HH*TT*HD];
__device__ float g_v[BB*HH*TT*HD];
__device__ float g_y[BB*TT*CC];      // [B,T,C]

// SW128 swizzle (bits[6:4] ^= bits[9:7]); 16B chunks stay contiguous
#define SW128(off)    ((off) ^ (((off) >> 3) & 0x70))

__device__ __forceinline__ uint32_t smem_u32(const void* p) {
    uint32_t a;
    asm("{ .reg .u64 t; cvta.to.shared.u64 t, %1; cvt.u32.u64 %0, t; }" : "=r"(a) : "l"(p));
    return a;
}

#define LDSM_X4(r0, r1, r2, r3, addr) \
    asm volatile("ldmatrix.sync.aligned.m8n8.x4.shared.b16 {%0,%1,%2,%3}, [%4];" \
                 : "=r"(r0), "=r"(r1), "=r"(r2), "=r"(r3) : "r"(addr))

#define MMA_BF16(d, a0, a1, a2, a3, b0, b1) \
    asm volatile("mma.sync.aligned.m16n8k16.row.col.f32.bf16.bf16.f32 " \
                 "{%0,%1,%2,%3}, {%4,%5,%6,%7}, {%8,%9}, {%0,%1,%2,%3};" \
                 : "+f"((d)[0]), "+f"((d)[1]), "+f"((d)[2]), "+f"((d)[3]) \
                 : "r"(a0), "r"(a1), "r"(a2), "r"(a3), "r"(b0), "r"(b1))

// ===========================================================================
// Tensor-core GEMM: C[m,n] = sum_k A[m,k]*B[n,k] + bias[n]
// A [M,K] fp32 row-major, B [N,K] fp32 row-major. Split-bf16 (hi+lo), 3 passes
// (hi*hi + hi*lo + lo*hi), fp32 accumulate -> rel_err ~1e-5.
// Tile 128x128, K-chunks of 64 bf16, 256 threads (8 warps, 64x32 per warp).
// MODE 1: QKV epilogue scatter into g_q/g_k/g_v. MODE 2: plain store (A := g_y).
// ===========================================================================
#define TCBM 128
#define TCBN 128
#define TCKC 64

// Dynamic smem layout (bytes): 4 tiles of 128 rows x 64 bf16 (128 B/row)
#define SM_AHI   0
#define SM_ALO   16384
#define SM_BHI   32768
#define SM_BLO   49152
#define SM_TOTAL 65536

__device__ __forceinline__ void load_tile_split(
    const float* __restrict__ src, int ldk, char* smem, int hi_off, int lo_off, int tid)
{
#pragma unroll
    for (int i = 0; i < 8; i++) {
        int idx = tid + i * 256;          // 0..2047 float4s: 128 rows x 16 float4
        int row = idx >> 4;
        int c4  = (idx & 15) << 2;        // float col, multiple of 4
        float4 v = *reinterpret_cast<const float4*>(src + (size_t)row * ldk + c4);

        __nv_bfloat16 hx = __float2bfloat16(v.x);
        __nv_bfloat16 hy = __float2bfloat16(v.y);
        __nv_bfloat16 hz = __float2bfloat16(v.z);
        __nv_bfloat16 hw = __float2bfloat16(v.w);
        __nv_bfloat16 lx = __float2bfloat16(v.x - __bfloat162float(hx));
        __nv_bfloat16 ly = __float2bfloat16(v.y - __bfloat162float(hy));
        __nv_bfloat16 lz = __float2bfloat16(v.z - __bfloat162float(hz));
        __nv_bfloat16 lw = __float2bfloat16(v.w - __bfloat162float(hw));

        uint32_t off = row * 128 + (c4 << 1);   // bf16 bytes, 8B aligned
        uint32_t sw  = SW128(off);
        __nv_bfloat162 h01; h01.x = hx; h01.y = hy;
        __nv_bfloat162 h23; h23.x = hz; h23.y = hw;
        __nv_bfloat162 l01; l01.x = lx; l01.y = ly;
        __nv_bfloat162 l23; l23.x = lz; l23.y = lw;
        *reinterpret_cast<__nv_bfloat162*>(smem + hi_off + sw)     = h01;
        *reinterpret_cast<__nv_bfloat162*>(smem + hi_off + sw + 4) = h23;
        *reinterpret_cast<__nv_bfloat162*>(smem + lo_off + sw)     = l01;
        *reinterpret_cast<__nv_bfloat162*>(smem + lo_off + sw + 4) = l23;
    }
}

template<int MODE>
__global__ __launch_bounds__(256) void gemm_tc(
    const float* __restrict__ A, const float* __restrict__ Bw,
    const float* __restrict__ bias, float* __restrict__ C,
    int K, int N)
{
    extern __shared__ char smem[];
    uint32_t sb  = smem_u32(smem);
    int tid = threadIdx.x;
    int wid = tid >> 5;
    int lid = tid & 31;

    const float* Ap = (MODE == 2) ? (const float*)g_y : A;
    int m0 = blockIdx.y * TCBM;
    int n0 = blockIdx.x * TCBN;

    int mw = (wid >> 2) * 64;    // warp M offset in tile
    int nw = (wid & 3)  * 32;    // warp N offset in tile

    // ldmatrix per-lane address constants
    int a_row = lid & 15;                           // A: matrix row within 16
    int a_cb  = (lid >> 4) * 16;                    // A: k-half byte offset
    int b_row = (lid & 7) + ((lid >> 4) << 3);      // B: n row within 16
    int b_cb  = ((lid >> 3) & 1) * 16;              // B: k-half byte offset

    float acc[16][4];            // [mi*4+ni][d0..d3]
#pragma unroll
    for (int i = 0; i < 16; i++)
#pragma unroll
        for (int j = 0; j < 4; j++) acc[i][j] = 0.f;

    const int nchunk = K / TCKC;
    for (int kc = 0; kc < nchunk; kc++) {
        load_tile_split(Ap + (size_t)m0 * K + kc * TCKC, K, smem, SM_AHI, SM_ALO, tid);
        load_tile_split(Bw + (size_t)n0 * K + kc * TCKC, K, smem, SM_BHI, SM_BLO, tid);
        __syncthreads();

#pragma unroll
        for (int p = 0; p < 3; p++) {
            uint32_t abase = sb + (p == 2 ? SM_ALO : SM_AHI);
            uint32_t bbase = sb + (p == 1 ? SM_BLO : SM_BHI);
#pragma unroll
            for (int ks = 0; ks < 4; ks++) {
                uint32_t af[4][4];
#pragma unroll
                for (int mi = 0; mi < 4; mi++) {
                    uint32_t addr = abase +
                        SW128((uint32_t)((mw + mi*16 + a_row) * 128 + ks*32 + a_cb));
                    LDSM_X4(af[mi][0], af[mi][1], af[mi][2], af[mi][3], addr);
                }
                uint32_t bf[2][4];
#pragma unroll
                for (int nn = 0; nn < 2; nn++) {
                    uint32_t addr = bbase +
                        SW128((uint32_t)((nw + nn*16 + b_row) * 128 + ks*32 + b_cb));
                    LDSM_X4(bf[nn][0], bf[nn][1], bf[nn][2], bf[nn][3], addr);
                }
#pragma unroll
                for (int mi = 0; mi < 4; mi++)
#pragma unroll
                    for (int ni = 0; ni < 4; ni++) {
                        uint32_t bb0 = bf[ni >> 1][(ni & 1) * 2];
                        uint32_t bb1 = bf[ni >> 1][(ni & 1) * 2 + 1];
                        MMA_BF16(acc[mi*4+ni],
                                 af[mi][0], af[mi][1], af[mi][2], af[mi][3], bb0, bb1);
                    }
            }
        }
        __syncthreads();
    }

    // Epilogue: lane (g,t4) owns rows {g, g+8}, cols {2t4, 2t4+1} of each 16x8 tile
    int g  = lid >> 2;
    int t4 = lid & 3;
#pragma unroll
    for (int mi = 0; mi < 4; mi++) {
        int mrow0 = m0 + mw + mi*16 + g;
        int mrow1 = mrow0 + 8;
#pragma unroll
        for (int ni = 0; ni < 4; ni++) {
            int n = n0 + nw + ni*8 + 2*t4;
            float bv0 = bias[n], bv1 = bias[n+1];
            const float* a4 = acc[mi*4+ni];
            float2 v0; v0.x = a4[0] + bv0; v0.y = a4[1] + bv1;   // row mrow0
            float2 v1; v1.x = a4[2] + bv0; v1.y = a4[3] + bv1;   // row mrow1

            if (MODE == 1) {
                int which = n >> 10;
                int h = (n >> 6) & 15;
                int d = n & 63;
                float* base = (which == 0 ? g_q : which == 1 ? g_k : g_v);
                {
                    int bb = mrow0 >> 11, t = mrow0 & 2047;
                    *reinterpret_cast<float2*>(
                        base + ((((size_t)bb*HH + h)*TT) + t)*HD + d) = v0;
                }
                {
                    int bb = mrow1 >> 11, t = mrow1 & 2047;
                    *reinterpret_cast<float2*>(
                        base + ((((size_t)bb*HH + h)*TT) + t)*HD + d) = v1;
                }
            } else {
                *reinterpret_cast<float2*>(C + (size_t)mrow0 * N + n) = v0;
                *reinterpret_cast<float2*>(C + (size_t)mrow1 * N + n) = v1;
            }
        }
    }
}

// ---------------------------------------------------------------------------
// Flash attention (fp32, causal) — unchanged from passing round.
// Block = (64-row Q tile, one (b,h)). 64 threads, one thread per Q row.
// ---------------------------------------------------------------------------
__global__ __launch_bounds__(64) void attn_kernel()
{
    __shared__ float Ks[64*64];
    __shared__ float Vs[64*64];
    __shared__ float Ss[64*64];   // [j*64 + r] : thread-private column

    int r  = threadIdx.x;
    int bh = blockIdx.y;
    int q0 = blockIdx.x * 64;

    size_t headoff = (size_t)bh * (TT*HD);

    const float4* Qg = reinterpret_cast<const float4*>(g_q + headoff + (size_t)(q0 + r)*HD);
    float q[64], o[64];
#pragma unroll
    for (int i = 0; i < 16; i++) {
        float4 t4 = Qg[i];
        q[4*i+0] = t4.x; q[4*i+1] = t4.y; q[4*i+2] = t4.z; q[4*i+3] = t4.w;
    }
#pragma unroll
    for (int i = 0; i < 64; i++) o[i] = 0.f;

    float mprev = -INFINITY, l = 0.f;
    int ntiles = blockIdx.x + 1;

    for (int kt = 0; kt < ntiles; kt++) {
        const float4* Kg = reinterpret_cast<const float4*>(g_k + headoff + (size_t)kt*64*HD);
        const float4* Vg = reinterpret_cast<const float4*>(g_v + headoff + (size_t)kt*64*HD);
        float4* Ks4 = reinterpret_cast<float4*>(Ks);
        float4* Vs4 = reinterpret_cast<float4*>(Vs);
        for (int i = r; i < 1024; i += 64) { Ks4[i] = Kg[i]; Vs4[i] = Vg[i]; }
        __syncthreads();

        int lim = q0 + r - kt*64;
        float mt = mprev;

        for (int j = 0; j < 64; j++) {
            const float4* kr = reinterpret_cast<const float4*>(Ks + j*64);
            float s0 = 0.f, s1 = 0.f, s2 = 0.f, s3 = 0.f;
#pragma unroll
            for (int i = 0; i < 16; i++) {
                float4 kv = kr[i];
                s0 += q[4*i+0]*kv.x;
                s1 += q[4*i+1]*kv.y;
                s2 += q[4*i+2]*kv.z;
                s3 += q[4*i+3]*kv.w;
            }
            float s = ((s0 + s1) + (s2 + s3)) * 0.125f;
            s = (j <= lim) ? s : -INFINITY;
            mt = fmaxf(mt, s);
            Ss[j*64 + r] = s;
        }

        float alpha = __expf(mprev - mt);
        l *= alpha;
#pragma unroll
        for (int i = 0; i < 64; i++) o[i] *= alpha;

        for (int j = 0; j < 64; j++) {
            float p = __expf(Ss[j*64 + r] - mt);
            l += p;
            const float4* vr = reinterpret_cast<const float4*>(Vs + j*64);
#pragma unroll
            for (int i = 0; i < 16; i++) {
                float4 vv = vr[i];
                o[4*i+0] += p*vv.x;
                o[4*i+1] += p*vv.y;
                o[4*i+2] += p*vv.z;
                o[4*i+3] += p*vv.w;
            }
        }
        mprev = mt;
        __syncthreads();
    }

    float inv = 1.f / l;
    int b = bh >> 4, h = bh & 15;
    float* dst = g_y + (((size_t)b*TT + q0 + r)*CC) + h*HD;
    float4* dst4 = reinterpret_cast<float4*>(dst);
#pragma unroll
    for (int i = 0; i < 16; i++) {
        float4 ov;
        ov.x = o[4*i+0]*inv; ov.y = o[4*i+1]*inv;
        ov.z = o[4*i+2]*inv; ov.w = o[4*i+3]*inv;
        dst4[i] = ov;
    }
}

// ---------------------------------------------------------------------------
extern "C" void kernel_launch(void* const* d_in, const int* in_sizes, int n_in,
                              void* d_out, int out_size)
{
    const float* x      = (const float*)d_in[0];   // [B,T,C]
    const float* W_attn = (const float*)d_in[1];   // [3C,C]
    const float* b_attn = (const float*)d_in[2];   // [3C]
    const float* W_proj = (const float*)d_in[3];   // [C,C]
    const float* b_proj = (const float*)d_in[4];   // [C]
    float* out = (float*)d_out;                    // [B,T,C]

    cudaFuncSetAttribute(gemm_tc<1>, cudaFuncAttributeMaxDynamicSharedMemorySize, SM_TOTAL);
    cudaFuncSetAttribute(gemm_tc<2>, cudaFuncAttributeMaxDynamicSharedMemorySize, SM_TOTAL);

    // 1) QKV projection (mma.sync bf16-split) + head-split scatter
    gemm_tc<1><<<dim3(N_QKV/TCBN, M_TOT/TCBM), 256, SM_TOTAL>>>(x, W_attn, b_attn, nullptr,
                                                                CC, N_QKV);
    // 2) causal flash attention (fp32 SIMT)
    attn_kernel<<<dim3(TT/64, BB*HH), 64>>>();

    // 3) output projection (mma.sync bf16-split)
    gemm_tc<2><<<dim3(CC/TCBN, M_TOT/TCBM), 256, SM_TOTAL>>>(nullptr, W_proj, b_proj, out,
                                                             CC, CC);
}

// round 9
// speedup vs baseline: 3.0127x; 2.1143x over previous
#include <cuda_runtime.h>
#include <cuda_bf16.h>
#include <math.h>
#include <stdint.h>

// Problem constants
#define BB 2
#define TT 2048
#define CC 1024
#define HH 16
#define HD 64
#define M_TOT (BB*TT)        // 4096
#define N_QKV (3*CC)         // 3072

// Scratch (device globals: allocation-free)
// q/k/v stored as split bf16 (hi + lo), [B,H,T,64]
__device__ __nv_bfloat16 g_qh[BB*HH*TT*HD], g_ql[BB*HH*TT*HD];
__device__ __nv_bfloat16 g_kh[BB*HH*TT*HD], g_kl[BB*HH*TT*HD];
__device__ __nv_bfloat16 g_vh[BB*HH*TT*HD], g_vl[BB*HH*TT*HD];
__device__ float g_y[BB*TT*CC];      // [B,T,C] attention output (fp32)

// SW128 swizzle (bits[6:4] ^= bits[9:7]); 16B chunks stay contiguous
#define SW128(off)    ((off) ^ (((off) >> 3) & 0x70))

__device__ __forceinline__ uint32_t smem_u32(const void* p) {
    uint32_t a;
    asm("{ .reg .u64 t; cvta.to.shared.u64 t, %1; cvt.u32.u64 %0, t; }" : "=r"(a) : "l"(p));
    return a;
}

#define LDSM_X4(r0, r1, r2, r3, addr) \
    asm volatile("ldmatrix.sync.aligned.m8n8.x4.shared.b16 {%0,%1,%2,%3}, [%4];" \
                 : "=r"(r0), "=r"(r1), "=r"(r2), "=r"(r3) : "r"(addr))

#define LDSM_X4_T(r0, r1, r2, r3, addr) \
    asm volatile("ldmatrix.sync.aligned.m8n8.x4.trans.shared.b16 {%0,%1,%2,%3}, [%4];" \
                 : "=r"(r0), "=r"(r1), "=r"(r2), "=r"(r3) : "r"(addr))

#define MMA_BF16(d, a0, a1, a2, a3, b0, b1) \
    asm volatile("mma.sync.aligned.m16n8k16.row.col.f32.bf16.bf16.f32 " \
                 "{%0,%1,%2,%3}, {%4,%5,%6,%7}, {%8,%9}, {%0,%1,%2,%3};" \
                 : "+f"((d)[0]), "+f"((d)[1]), "+f"((d)[2]), "+f"((d)[3]) \
                 : "r"(a0), "r"(a1), "r"(a2), "r"(a3), "r"(b0), "r"(b1))

// hi/lo split helpers: hi = truncate-to-bf16 (exact in fp32), lo = rn(x - hi)
__device__ __forceinline__ float hi_trunc(float x) {
    return __uint_as_float(__float_as_uint(x) & 0xFFFF0000u);
}
// pack bf16x2: low half = bf16_trunc(x), high half = bf16_trunc(y)
__device__ __forceinline__ uint32_t pack2_hi(float x, float y) {
    return (__float_as_uint(x) >> 16) | (__float_as_uint(y) & 0xFFFF0000u);
}
// pack bf16x2 with round-to-nearest: low = rn(x), high = rn(y)
__device__ __forceinline__ uint32_t pack2_rn(float x, float y) {
    uint32_t r;
    asm("cvt.rn.bf16x2.f32 %0, %1, %2;" : "=r"(r) : "f"(y), "f"(x));
    return r;
}

// ===========================================================================
// Tensor-core GEMM: C[m,n] = sum_k A[m,k]*B[n,k] + bias[n]
// Split-bf16 3 passes. Tile 128x128, K-chunks of 64 bf16, 256 threads.
// MODE 1: QKV epilogue -> scatter bf16 hi/lo into g_{q,k,v}{h,l}.
// MODE 2: proj (A := g_y), fp32 store to C.
// ===========================================================================
#define TCBM 128
#define TCBN 128
#define TCKC 64

#define SM_AHI   0
#define SM_ALO   16384
#define SM_BHI   32768
#define SM_BLO   49152
#define SM_TOTAL 65536

__device__ __forceinline__ void load_tile_split(
    const float* __restrict__ src, int ldk, char* smem, int hi_off, int lo_off, int tid)
{
#pragma unroll
    for (int i = 0; i < 8; i++) {
        int idx = tid + i * 256;
        int row = idx >> 4;
        int c4  = (idx & 15) << 2;
        float4 v = *reinterpret_cast<const float4*>(src + (size_t)row * ldk + c4);

        __nv_bfloat16 hx = __float2bfloat16(v.x);
        __nv_bfloat16 hy = __float2bfloat16(v.y);
        __nv_bfloat16 hz = __float2bfloat16(v.z);
        __nv_bfloat16 hw = __float2bfloat16(v.w);
        __nv_bfloat16 lx = __float2bfloat16(v.x - __bfloat162float(hx));
        __nv_bfloat16 ly = __float2bfloat16(v.y - __bfloat162float(hy));
        __nv_bfloat16 lz = __float2bfloat16(v.z - __bfloat162float(hz));
        __nv_bfloat16 lw = __float2bfloat16(v.w - __bfloat162float(hw));

        uint32_t off = row * 128 + (c4 << 1);
        uint32_t sw  = SW128(off);
        __nv_bfloat162 h01; h01.x = hx; h01.y = hy;
        __nv_bfloat162 h23; h23.x = hz; h23.y = hw;
        __nv_bfloat162 l01; l01.x = lx; l01.y = ly;
        __nv_bfloat162 l23; l23.x = lz; l23.y = lw;
        *reinterpret_cast<__nv_bfloat162*>(smem + hi_off + sw)     = h01;
        *reinterpret_cast<__nv_bfloat162*>(smem + hi_off + sw + 4) = h23;
        *reinterpret_cast<__nv_bfloat162*>(smem + lo_off + sw)     = l01;
        *reinterpret_cast<__nv_bfloat162*>(smem + lo_off + sw + 4) = l23;
    }
}

template<int MODE>
__global__ __launch_bounds__(256) void gemm_tc(
    const float* __restrict__ A, const float* __restrict__ Bw,
    const float* __restrict__ bias, float* __restrict__ C,
    int K, int N)
{
    extern __shared__ char smem[];
    uint32_t sb  = smem_u32(smem);
    int tid = threadIdx.x;
    int wid = tid >> 5;
    int lid = tid & 31;

    const float* Ap = (MODE == 2) ? (const float*)g_y : A;
    int m0 = blockIdx.y * TCBM;
    int n0 = blockIdx.x * TCBN;

    int mw = (wid >> 2) * 64;
    int nw = (wid & 3)  * 32;

    int a_row = lid & 15;
    int a_cb  = (lid >> 4) * 16;
    int b_row = (lid & 7) + ((lid >> 4) << 3);
    int b_cb  = ((lid >> 3) & 1) * 16;

    float acc[16][4];
#pragma unroll
    for (int i = 0; i < 16; i++)
#pragma unroll
        for (int j = 0; j < 4; j++) acc[i][j] = 0.f;

    const int nchunk = K / TCKC;
    for (int kc = 0; kc < nchunk; kc++) {
        load_tile_split(Ap + (size_t)m0 * K + kc * TCKC, K, smem, SM_AHI, SM_ALO, tid);
        load_tile_split(Bw + (size_t)n0 * K + kc * TCKC, K, smem, SM_BHI, SM_BLO, tid);
        __syncthreads();

#pragma unroll
        for (int p = 0; p < 3; p++) {
            uint32_t abase = sb + (p == 2 ? SM_ALO : SM_AHI);
            uint32_t bbase = sb + (p == 1 ? SM_BLO : SM_BHI);
#pragma unroll
            for (int ks = 0; ks < 4; ks++) {
                uint32_t af[4][4];
#pragma unroll
                for (int mi = 0; mi < 4; mi++) {
                    uint32_t addr = abase +
                        SW128((uint32_t)((mw + mi*16 + a_row) * 128 + ks*32 + a_cb));
                    LDSM_X4(af[mi][0], af[mi][1], af[mi][2], af[mi][3], addr);
                }
                uint32_t bf[2][4];
#pragma unroll
                for (int nn = 0; nn < 2; nn++) {
                    uint32_t addr = bbase +
                        SW128((uint32_t)((nw + nn*16 + b_row) * 128 + ks*32 + b_cb));
                    LDSM_X4(bf[nn][0], bf[nn][1], bf[nn][2], bf[nn][3], addr);
                }
#pragma unroll
                for (int mi = 0; mi < 4; mi++)
#pragma unroll
                    for (int ni = 0; ni < 4; ni++) {
                        uint32_t bb0 = bf[ni >> 1][(ni & 1) * 2];
                        uint32_t bb1 = bf[ni >> 1][(ni & 1) * 2 + 1];
                        MMA_BF16(acc[mi*4+ni],
                                 af[mi][0], af[mi][1], af[mi][2], af[mi][3], bb0, bb1);
                    }
            }
        }
        __syncthreads();
    }

    int g  = lid >> 2;
    int t4 = lid & 3;
#pragma unroll
    for (int mi = 0; mi < 4; mi++) {
        int mrow0 = m0 + mw + mi*16 + g;
        int mrow1 = mrow0 + 8;
#pragma unroll
        for (int ni = 0; ni < 4; ni++) {
            int n = n0 + nw + ni*8 + 2*t4;
            float bv0 = bias[n], bv1 = bias[n+1];
            const float* a4 = acc[mi*4+ni];
            float2 v0; v0.x = a4[0] + bv0; v0.y = a4[1] + bv1;
            float2 v1; v1.x = a4[2] + bv0; v1.y = a4[3] + bv1;

            if (MODE == 1) {
                int which = n >> 10;
                int h = (n >> 6) & 15;
                int d = n & 63;
                __nv_bfloat16* ph_ = (which == 0 ? g_qh : which == 1 ? g_kh : g_vh);
                __nv_bfloat16* pl_ = (which == 0 ? g_ql : which == 1 ? g_kl : g_vl);
                {
                    int bb = mrow0 >> 11, t = mrow0 & 2047;
                    size_t i0 = ((((size_t)bb*HH + h)*TT) + t)*HD + d;
                    ((uint32_t*)ph_)[i0 >> 1] = pack2_hi(v0.x, v0.y);
                    ((uint32_t*)pl_)[i0 >> 1] =
                        pack2_rn(v0.x - hi_trunc(v0.x), v0.y - hi_trunc(v0.y));
                }
                {
                    int bb = mrow1 >> 11, t = mrow1 & 2047;
                    size_t i1 = ((((size_t)bb*HH + h)*TT) + t)*HD + d;
                    ((uint32_t*)ph_)[i1 >> 1] = pack2_hi(v1.x, v1.y);
                    ((uint32_t*)pl_)[i1 >> 1] =
                        pack2_rn(v1.x - hi_trunc(v1.x), v1.y - hi_trunc(v1.y));
                }
            } else {
                *reinterpret_cast<float2*>(C + (size_t)mrow0 * N + n) = v0;
                *reinterpret_cast<float2*>(C + (size_t)mrow1 * N + n) = v1;
            }
        }
    }
}

// ===========================================================================
// Tensor-core flash attention (causal). Block = 64 q-rows x one (b,h),
// 4 warps (128 thr), warp w owns q rows [w*16, w*16+16).
// S = QK^T: 3 split passes; P split hi/lo in registers; PV: 3 split passes
// with ldmatrix.trans on V. fp32 accumulators + online softmax.
// ===========================================================================
__global__ __launch_bounds__(128) void attn_tc()
{
    __shared__ __align__(1024) char sKh[8192];
    __shared__ __align__(1024) char sKl[8192];
    __shared__ __align__(1024) char sVh[8192];
    __shared__ __align__(1024) char sVl[8192];

    int tid = threadIdx.x;
    int wid = tid >> 5;
    int lid = tid & 31;
    int qt  = blockIdx.x;
    int bh  = blockIdx.y;
    int q0  = qt * 64;
    size_t hoff = (size_t)bh * (TT * HD);

    uint32_t skh = smem_u32(sKh), skl = smem_u32(sKl);
    uint32_t svh = smem_u32(sVh), svl = smem_u32(sVl);

    int g  = lid >> 2;
    int t4 = lid & 3;

    // ---- stage Q tile (hi->sKh, lo->sKl), then build Q fragments ----
    {
        const uint4* srch = reinterpret_cast<const uint4*>(g_qh + hoff + (size_t)q0*HD);
        const uint4* srcl = reinterpret_cast<const uint4*>(g_ql + hoff + (size_t)q0*HD);
#pragma unroll
        for (int i = 0; i < 4; i++) {
            int idx = tid + i*128;          // 512 uint4 = 64 rows x 8 chunks
            int row = idx >> 3, ch = idx & 7;
            uint32_t sw = SW128((uint32_t)(row*128 + ch*16));
            *reinterpret_cast<uint4*>(sKh + sw) = srch[row*8 + ch];
            *reinterpret_cast<uint4*>(sKl + sw) = srcl[row*8 + ch];
        }
    }
    __syncthreads();

    uint32_t qh[4][4], ql[4][4];
    int a_row = lid & 15, a_cb = (lid >> 4) * 16;
#pragma unroll
    for (int ks = 0; ks < 4; ks++) {
        uint32_t off = SW128((uint32_t)((wid*16 + a_row)*128 + ks*32 + a_cb));
        LDSM_X4(qh[ks][0], qh[ks][1], qh[ks][2], qh[ks][3], skh + off);
        LDSM_X4(ql[ks][0], ql[ks][1], ql[ks][2], ql[ks][3], skl + off);
    }
    __syncthreads();

    float o[8][4];
#pragma unroll
    for (int i = 0; i < 8; i++)
#pragma unroll
        for (int j = 0; j < 4; j++) o[i][j] = 0.f;
    float m0 = -INFINITY, m1 = -INFINITY, l0 = 0.f, l1 = 0.f;

    int b_row = (lid & 7) + ((lid >> 4) << 3);
    int b_cb  = ((lid >> 3) & 1) * 16;
    int v_row = (lid & 7) + (((lid >> 3) & 1) << 3);
    int v_cb  = (lid >> 4) << 4;

    for (int kt = 0; kt <= qt; kt++) {
        // stage K/V tiles (bf16 hi/lo)
        {
            const uint4* kh4 = reinterpret_cast<const uint4*>(g_kh + hoff + (size_t)kt*64*HD);
            const uint4* kl4 = reinterpret_cast<const uint4*>(g_kl + hoff + (size_t)kt*64*HD);
            const uint4* vh4 = reinterpret_cast<const uint4*>(g_vh + hoff + (size_t)kt*64*HD);
            const uint4* vl4 = reinterpret_cast<const uint4*>(g_vl + hoff + (size_t)kt*64*HD);
#pragma unroll
            for (int i = 0; i < 4; i++) {
                int idx = tid + i*128;
                int row = idx >> 3, ch = idx & 7;
                uint32_t sw = SW128((uint32_t)(row*128 + ch*16));
                int si = row*8 + ch;
                *reinterpret_cast<uint4*>(sKh + sw) = kh4[si];
                *reinterpret_cast<uint4*>(sKl + sw) = kl4[si];
                *reinterpret_cast<uint4*>(sVh + sw) = vh4[si];
                *reinterpret_cast<uint4*>(sVl + sw) = vl4[si];
            }
        }
        __syncthreads();

        // ---- S = Q K^T (3 passes) ----
        float s[8][4];
#pragma unroll
        for (int i = 0; i < 8; i++)
#pragma unroll
            for (int j = 0; j < 4; j++) s[i][j] = 0.f;

#pragma unroll
        for (int ks = 0; ks < 4; ks++) {
#pragma unroll
            for (int nn = 0; nn < 4; nn++) {
                uint32_t off = SW128((uint32_t)((nn*16 + b_row)*128 + ks*32 + b_cb));
                uint32_t k0, k1, k2, k3, c0, c1, c2, c3;
                LDSM_X4(k0, k1, k2, k3, skh + off);
                LDSM_X4(c0, c1, c2, c3, skl + off);
                MMA_BF16(s[nn*2],   qh[ks][0], qh[ks][1], qh[ks][2], qh[ks][3], k0, k1);
                MMA_BF16(s[nn*2+1], qh[ks][0], qh[ks][1], qh[ks][2], qh[ks][3], k2, k3);
                MMA_BF16(s[nn*2],   qh[ks][0], qh[ks][1], qh[ks][2], qh[ks][3], c0, c1);
                MMA_BF16(s[nn*2+1], qh[ks][0], qh[ks][1], qh[ks][2], qh[ks][3], c2, c3);
                MMA_BF16(s[nn*2],   ql[ks][0], ql[ks][1], ql[ks][2], ql[ks][3], k0, k1);
                MMA_BF16(s[nn*2+1], ql[ks][0], ql[ks][1], ql[ks][2], ql[ks][3], k2, k3);
            }
        }

        // ---- scale + causal mask ----
        if (kt == qt) {
#pragma unroll
            for (int ni = 0; ni < 8; ni++)
#pragma unroll
                for (int j = 0; j < 4; j++) {
                    int ct = ni*8 + 2*t4 + (j & 1);
                    int rt = wid*16 + g + ((j >> 1) << 3);
                    s[ni][j] = (ct <= rt) ? s[ni][j] * 0.125f : -INFINITY;
                }
        } else {
#pragma unroll
            for (int ni = 0; ni < 8; ni++)
#pragma unroll
                for (int j = 0; j < 4; j++) s[ni][j] *= 0.125f;
        }

        // ---- online softmax ----
        float mt0 = m0, mt1 = m1;
#pragma unroll
        for (int ni = 0; ni < 8; ni++) {
            mt0 = fmaxf(mt0, fmaxf(s[ni][0], s[ni][1]));
            mt1 = fmaxf(mt1, fmaxf(s[ni][2], s[ni][3]));
        }
        mt0 = fmaxf(mt0, __shfl_xor_sync(0xffffffffu, mt0, 1));
        mt0 = fmaxf(mt0, __shfl_xor_sync(0xffffffffu, mt0, 2));
        mt1 = fmaxf(mt1, __shfl_xor_sync(0xffffffffu, mt1, 1));
        mt1 = fmaxf(mt1, __shfl_xor_sync(0xffffffffu, mt1, 2));

        float alpha0 = __expf(m0 - mt0);
        float alpha1 = __expf(m1 - mt1);
        m0 = mt0; m1 = mt1;

        float ps0 = 0.f, ps1 = 0.f;
#pragma unroll
        for (int ni = 0; ni < 8; ni++) {
            s[ni][0] = __expf(s[ni][0] - m0);
            s[ni][1] = __expf(s[ni][1] - m0);
            s[ni][2] = __expf(s[ni][2] - m1);
            s[ni][3] = __expf(s[ni][3] - m1);
            ps0 += s[ni][0] + s[ni][1];
            ps1 += s[ni][2] + s[ni][3];
        }
        ps0 += __shfl_xor_sync(0xffffffffu, ps0, 1);
        ps0 += __shfl_xor_sync(0xffffffffu, ps0, 2);
        ps1 += __shfl_xor_sync(0xffffffffu, ps1, 1);
        ps1 += __shfl_xor_sync(0xffffffffu, ps1, 2);
        l0 = l0 * alpha0 + ps0;
        l1 = l1 * alpha1 + ps1;

#pragma unroll
        for (int dt = 0; dt < 8; dt++) {
            o[dt][0] *= alpha0; o[dt][1] *= alpha0;
            o[dt][2] *= alpha1; o[dt][3] *= alpha1;
        }

        // ---- P fragments (C-layout == A-layout), split hi/lo in regs ----
        uint32_t ph[4][4], pl[4][4];
#pragma unroll
        for (int kc = 0; kc < 4; kc++) {
            float x0 = s[2*kc][0],   x1 = s[2*kc][1],   x2 = s[2*kc][2],   x3 = s[2*kc][3];
            float y0 = s[2*kc+1][0], y1 = s[2*kc+1][1], y2 = s[2*kc+1][2], y3 = s[2*kc+1][3];
            ph[kc][0] = pack2_hi(x0, x1);
            ph[kc][1] = pack2_hi(x2, x3);
            ph[kc][2] = pack2_hi(y0, y1);
            ph[kc][3] = pack2_hi(y2, y3);
            pl[kc][0] = pack2_rn(x0 - hi_trunc(x0), x1 - hi_trunc(x1));
            pl[kc][1] = pack2_rn(x2 - hi_trunc(x2), x3 - hi_trunc(x3));
            pl[kc][2] = pack2_rn(y0 - hi_trunc(y0), y1 - hi_trunc(y1));
            pl[kc][3] = pack2_rn(y2 - hi_trunc(y2), y3 - hi_trunc(y3));
        }

        // ---- O += P V (3 passes, V via ldmatrix.trans) ----
#pragma unroll
        for (int kc = 0; kc < 4; kc++) {
#pragma unroll
            for (int dn = 0; dn < 4; dn++) {
                uint32_t off = SW128((uint32_t)((kc*16 + v_row)*128 + dn*32 + v_cb));
                uint32_t vh0, vh1, vh2, vh3, vl0, vl1, vl2, vl3;
                LDSM_X4_T(vh0, vh1, vh2, vh3, svh + off);
                LDSM_X4_T(vl0, vl1, vl2, vl3, svl + off);
                MMA_BF16(o[dn*2],   ph[kc][0], ph[kc][1], ph[kc][2], ph[kc][3], vh0, vh1);
                MMA_BF16(o[dn*2+1], ph[kc][0], ph[kc][1], ph[kc][2], ph[kc][3], vh2, vh3);
                MMA_BF16(o[dn*2],   ph[kc][0], ph[kc][1], ph[kc][2], ph[kc][3], vl0, vl1);
                MMA_BF16(o[dn*2+1], ph[kc][0], ph[kc][1], ph[kc][2], ph[kc][3], vl2, vl3);
                MMA_BF16(o[dn*2],   pl[kc][0], pl[kc][1], pl[kc][2], pl[kc][3], vh0, vh1);
                MMA_BF16(o[dn*2+1], pl[kc][0], pl[kc][1], pl[kc][2], pl[kc][3], vh2, vh3);
            }
        }
        __syncthreads();   // before next tile overwrites K/V smem
    }

    // ---- epilogue: normalize, write to g_y [B,T,C] ----
    float inv0 = 1.f / l0, inv1 = 1.f / l1;
    int b = bh >> 4, h = bh & 15;
    int row0 = q0 + wid*16 + g;
    int row1 = row0 + 8;
    float* y0p = g_y + ((size_t)b*TT + row0)*CC + h*HD;
    float* y1p = g_y + ((size_t)b*TT + row1)*CC + h*HD;
#pragma unroll
    for (int dt = 0; dt < 8; dt++) {
        int d = dt*8 + 2*t4;
        float2 w0; w0.x = o[dt][0]*inv0; w0.y = o[dt][1]*inv0;
        float2 w1; w1.x = o[dt][2]*inv1; w1.y = o[dt][3]*inv1;
        *reinterpret_cast<float2*>(y0p + d) = w0;
        *reinterpret_cast<float2*>(y1p + d) = w1;
    }
}

// ---------------------------------------------------------------------------
extern "C" void kernel_launch(void* const* d_in, const int* in_sizes, int n_in,
                              void* d_out, int out_size)
{
    const float* x      = (const float*)d_in[0];   // [B,T,C]
    const float* W_attn = (const float*)d_in[1];   // [3C,C]
    const float* b_attn = (const float*)d_in[2];   // [3C]
    const float* W_proj = (const float*)d_in[3];   // [C,C]
    const float* b_proj = (const float*)d_in[4];   // [C]
    float* out = (float*)d_out;                    // [B,T,C]

    cudaFuncSetAttribute(gemm_tc<1>, cudaFuncAttributeMaxDynamicSharedMemorySize, SM_TOTAL);
    cudaFuncSetAttribute(gemm_tc<2>, cudaFuncAttributeMaxDynamicSharedMemorySize, SM_TOTAL);

    // 1) QKV projection (mma.sync bf16-split) -> q/k/v bf16 hi/lo scatter
    gemm_tc<1><<<dim3(N_QKV/TCBN, M_TOT/TCBM), 256, SM_TOTAL>>>(x, W_attn, b_attn, nullptr,
                                                                CC, N_QKV);
    // 2) causal flash attention (tensor cores, split-bf16)
    attn_tc<<<dim3(TT/64, BB*HH), 128>>>();

    // 3) output projection (mma.sync bf16-split)
    gemm_tc<2><<<dim3(CC/TCBN, M_TOT/TCBM), 256, SM_TOTAL>>>(nullptr, W_proj, b_proj, out,
                                                             CC, CC);
}

// round 10
// speedup vs baseline: 3.5971x; 1.1940x over previous
#include <cuda_runtime.h>
#include <cuda_bf16.h>
#include <math.h>
#include <stdint.h>

// Problem constants
#define BB 2
#define TT 2048
#define CC 1024
#define HH 16
#define HD 64
#define M_TOT (BB*TT)        // 4096
#define N_QKV (3*CC)         // 3072

// Scratch (device globals: allocation-free)
// pre-split bf16 operands
__device__ __nv_bfloat16 g_xh[M_TOT*CC],  g_xl[M_TOT*CC];     // x  [4096,1024]
__device__ __nv_bfloat16 g_wah[N_QKV*CC], g_wal[N_QKV*CC];    // W_attn [3072,1024]
__device__ __nv_bfloat16 g_wph[CC*CC],    g_wpl[CC*CC];       // W_proj [1024,1024]
// q/k/v split bf16, [B,H,T,64]
__device__ __nv_bfloat16 g_qh[BB*HH*TT*HD], g_ql[BB*HH*TT*HD];
__device__ __nv_bfloat16 g_kh[BB*HH*TT*HD], g_kl[BB*HH*TT*HD];
__device__ __nv_bfloat16 g_vh[BB*HH*TT*HD], g_vl[BB*HH*TT*HD];
// attention output, split bf16, [B,T,C]
__device__ __nv_bfloat16 g_yh[BB*TT*CC], g_yl[BB*TT*CC];

// SW128 swizzle (bits[6:4] ^= bits[9:7]); 16B chunks stay contiguous
#define SW128(off)    ((off) ^ (((off) >> 3) & 0x70))

__device__ __forceinline__ uint32_t smem_u32(const void* p) {
    uint32_t a;
    asm("{ .reg .u64 t; cvta.to.shared.u64 t, %1; cvt.u32.u64 %0, t; }" : "=r"(a) : "l"(p));
    return a;
}

#define LDSM_X4(r0, r1, r2, r3, addr) \
    asm volatile("ldmatrix.sync.aligned.m8n8.x4.shared.b16 {%0,%1,%2,%3}, [%4];" \
                 : "=r"(r0), "=r"(r1), "=r"(r2), "=r"(r3) : "r"(addr))

#define LDSM_X4_T(r0, r1, r2, r3, addr) \
    asm volatile("ldmatrix.sync.aligned.m8n8.x4.trans.shared.b16 {%0,%1,%2,%3}, [%4];" \
                 : "=r"(r0), "=r"(r1), "=r"(r2), "=r"(r3) : "r"(addr))

#define MMA_BF16(d, a0, a1, a2, a3, b0, b1) \
    asm volatile("mma.sync.aligned.m16n8k16.row.col.f32.bf16.bf16.f32 " \
                 "{%0,%1,%2,%3}, {%4,%5,%6,%7}, {%8,%9}, {%0,%1,%2,%3};" \
                 : "+f"((d)[0]), "+f"((d)[1]), "+f"((d)[2]), "+f"((d)[3]) \
                 : "r"(a0), "r"(a1), "r"(a2), "r"(a3), "r"(b0), "r"(b1))

__device__ __forceinline__ void cp16(uint32_t dst, const void* src) {
    asm volatile("cp.async.cg.shared.global [%0], [%1], 16;" :: "r"(dst), "l"(src));
}
#define CP_COMMIT()   asm volatile("cp.async.commit_group;" ::: "memory")
#define CP_WAIT(n)    asm volatile("cp.async.wait_group %0;" :: "n"(n) : "memory")

// hi/lo split helpers
__device__ __forceinline__ float hi_trunc(float x) {
    return __uint_as_float(__float_as_uint(x) & 0xFFFF0000u);
}
__device__ __forceinline__ uint32_t pack2_hi(float x, float y) {
    return (__float_as_uint(x) >> 16) | (__float_as_uint(y) & 0xFFFF0000u);
}
__device__ __forceinline__ uint32_t pack2_rn(float x, float y) {
    uint32_t r;
    asm("cvt.rn.bf16x2.f32 %0, %1, %2;" : "=r"(r) : "f"(y), "f"(x));
    return r;
}

// ===========================================================================
// One-time fp32 -> bf16 hi/lo split (grid-strided, float4 granularity)
// ===========================================================================
__global__ __launch_bounds__(256) void convert_split(
    const float4* __restrict__ src, uint32_t* __restrict__ hi,
    uint32_t* __restrict__ lo, int n4)
{
    int i = blockIdx.x * blockDim.x + threadIdx.x;
    if (i >= n4) return;
    float4 v = src[i];
    uint2 h, l;
    h.x = pack2_hi(v.x, v.y);
    h.y = pack2_hi(v.z, v.w);
    l.x = pack2_rn(v.x - hi_trunc(v.x), v.y - hi_trunc(v.y));
    l.y = pack2_rn(v.z - hi_trunc(v.z), v.w - hi_trunc(v.w));
    reinterpret_cast<uint2*>(hi)[i] = h;
    reinterpret_cast<uint2*>(lo)[i] = l;
}

// ===========================================================================
// Pipelined tensor-core GEMM on pre-split bf16: C = A B^T + bias.
// Tile 128x128, K-chunks of 64, cp.async double-buffered smem, 256 threads.
// MODE 1: A=g_x*, B=g_wa*; epilogue scatters q/k/v bf16 hi/lo.
// MODE 2: A=g_y*, B=g_wp*; epilogue stores fp32 to C.
// ===========================================================================
#define SM_BUF   65536          // one buffer: 4 tiles x 16 KB
#define SM_TOTAL (2*SM_BUF)     // 128 KB

template<int MODE>
__global__ __launch_bounds__(256) void gemm_tc(
    const float* __restrict__ bias, float* __restrict__ C, int K, int N)
{
    extern __shared__ char smem[];
    uint32_t sb  = smem_u32(smem);
    int tid = threadIdx.x;
    int wid = tid >> 5;
    int lid = tid & 31;

    const __nv_bfloat16 *Ah, *Al, *Bh, *Bl;
    if (MODE == 1) { Ah = g_xh; Al = g_xl; Bh = g_wah; Bl = g_wal; }
    else           { Ah = g_yh; Al = g_yl; Bh = g_wph; Bl = g_wpl; }

    int m0 = blockIdx.y * 128;
    int n0 = blockIdx.x * 128;

    int mw = (wid >> 2) * 64;
    int nw = (wid & 3)  * 32;

    int a_row = lid & 15;
    int a_cb  = (lid >> 4) * 16;
    int b_row = (lid & 7) + ((lid >> 4) << 3);
    int b_cb  = ((lid >> 3) & 1) * 16;

    // per-thread staging addresses: 4 x 16B per tile
    int s_row[4], s_ch[4];
#pragma unroll
    for (int i = 0; i < 4; i++) {
        int idx = tid + i * 256;        // 1024 chunks: 128 rows x 8 x 16B
        s_row[i] = idx >> 3;
        s_ch[i]  = idx & 7;
    }

    const int nchunk = K / 64;

    // stage chunk kc into buffer buf
    auto stage = [&](int kc, int buf) {
        uint32_t base = sb + buf * SM_BUF;
        const __nv_bfloat16* srcs[4] = {
            Ah + (size_t)m0 * K + kc * 64, Al + (size_t)m0 * K + kc * 64,
            Bh + (size_t)n0 * K + kc * 64, Bl + (size_t)n0 * K + kc * 64 };
#pragma unroll
        for (int t = 0; t < 4; t++)
#pragma unroll
            for (int i = 0; i < 4; i++)
                cp16(base + t * 16384 + SW128((uint32_t)(s_row[i]*128 + s_ch[i]*16)),
                     srcs[t] + (size_t)s_row[i] * K + s_ch[i] * 8);
        CP_COMMIT();
    };

    float acc[16][4];
#pragma unroll
    for (int i = 0; i < 16; i++)
#pragma unroll
        for (int j = 0; j < 4; j++) acc[i][j] = 0.f;

    stage(0, 0);

    for (int kc = 0; kc < nchunk; kc++) {
        int cur = kc & 1;
        if (kc + 1 < nchunk) { stage(kc + 1, cur ^ 1); CP_WAIT(1); }
        else                 { CP_WAIT(0); }
        __syncthreads();                 // staged data of 'cur' visible to all

        uint32_t bufb = sb + cur * SM_BUF;
#pragma unroll
        for (int p = 0; p < 3; p++) {
            uint32_t abase = bufb + (p == 2 ? 16384 : 0);
            uint32_t bbase = bufb + (p == 1 ? 49152 : 32768);
#pragma unroll
            for (int ks = 0; ks < 4; ks++) {
                uint32_t af[4][4];
#pragma unroll
                for (int mi = 0; mi < 4; mi++) {
                    uint32_t addr = abase +
                        SW128((uint32_t)((mw + mi*16 + a_row) * 128 + ks*32 + a_cb));
                    LDSM_X4(af[mi][0], af[mi][1], af[mi][2], af[mi][3], addr);
                }
                uint32_t bf[2][4];
#pragma unroll
                for (int nn = 0; nn < 2; nn++) {
                    uint32_t addr = bbase +
                        SW128((uint32_t)((nw + nn*16 + b_row) * 128 + ks*32 + b_cb));
                    LDSM_X4(bf[nn][0], bf[nn][1], bf[nn][2], bf[nn][3], addr);
                }
#pragma unroll
                for (int mi = 0; mi < 4; mi++)
#pragma unroll
                    for (int ni = 0; ni < 4; ni++) {
                        uint32_t bb0 = bf[ni >> 1][(ni & 1) * 2];
                        uint32_t bb1 = bf[ni >> 1][(ni & 1) * 2 + 1];
                        MMA_BF16(acc[mi*4+ni],
                                 af[mi][0], af[mi][1], af[mi][2], af[mi][3], bb0, bb1);
                    }
            }
        }
        __syncthreads();                 // all warps done with 'cur' before overwrite
    }

    int g  = lid >> 2;
    int t4 = lid & 3;
#pragma unroll
    for (int mi = 0; mi < 4; mi++) {
        int mrow0 = m0 + mw + mi*16 + g;
        int mrow1 = mrow0 + 8;
#pragma unroll
        for (int ni = 0; ni < 4; ni++) {
            int n = n0 + nw + ni*8 + 2*t4;
            float bv0 = bias[n], bv1 = bias[n+1];
            const float* a4 = acc[mi*4+ni];
            float2 v0; v0.x = a4[0] + bv0; v0.y = a4[1] + bv1;
            float2 v1; v1.x = a4[2] + bv0; v1.y = a4[3] + bv1;

            if (MODE == 1) {
                int which = n >> 10;
                int h = (n >> 6) & 15;
                int d = n & 63;
                __nv_bfloat16* ph_ = (which == 0 ? g_qh : which == 1 ? g_kh : g_vh);
                __nv_bfloat16* pl_ = (which == 0 ? g_ql : which == 1 ? g_kl : g_vl);
                {
                    int bb = mrow0 >> 11, t = mrow0 & 2047;
                    size_t i0 = ((((size_t)bb*HH + h)*TT) + t)*HD + d;
                    ((uint32_t*)ph_)[i0 >> 1] = pack2_hi(v0.x, v0.y);
                    ((uint32_t*)pl_)[i0 >> 1] =
                        pack2_rn(v0.x - hi_trunc(v0.x), v0.y - hi_trunc(v0.y));
                }
                {
                    int bb = mrow1 >> 11, t = mrow1 & 2047;
                    size_t i1 = ((((size_t)bb*HH + h)*TT) + t)*HD + d;
                    ((uint32_t*)ph_)[i1 >> 1] = pack2_hi(v1.x, v1.y);
                    ((uint32_t*)pl_)[i1 >> 1] =
                        pack2_rn(v1.x - hi_trunc(v1.x), v1.y - hi_trunc(v1.y));
                }
            } else {
                *reinterpret_cast<float2*>(C + (size_t)mrow0 * N + n) = v0;
                *reinterpret_cast<float2*>(C + (size_t)mrow1 * N + n) = v1;
            }
        }
    }
}

// ===========================================================================
// Tensor-core flash attention (causal) — unchanged mainloop; epilogue now
// writes split bf16 into g_yh/g_yl for the proj GEMM.
// ===========================================================================
__global__ __launch_bounds__(128) void attn_tc()
{
    __shared__ __align__(1024) char sKh[8192];
    __shared__ __align__(1024) char sKl[8192];
    __shared__ __align__(1024) char sVh[8192];
    __shared__ __align__(1024) char sVl[8192];

    int tid = threadIdx.x;
    int wid = tid >> 5;
    int lid = tid & 31;
    int qt  = blockIdx.x;
    int bh  = blockIdx.y;
    int q0  = qt * 64;
    size_t hoff = (size_t)bh * (TT * HD);

    uint32_t skh = smem_u32(sKh), skl = smem_u32(sKl);
    uint32_t svh = smem_u32(sVh), svl = smem_u32(sVl);

    int g  = lid >> 2;
    int t4 = lid & 3;

    // ---- stage Q tile (hi->sKh, lo->sKl), then build Q fragments ----
    {
        const uint4* srch = reinterpret_cast<const uint4*>(g_qh + hoff + (size_t)q0*HD);
        const uint4* srcl = reinterpret_cast<const uint4*>(g_ql + hoff + (size_t)q0*HD);
#pragma unroll
        for (int i = 0; i < 4; i++) {
            int idx = tid + i*128;
            int row = idx >> 3, ch = idx & 7;
            uint32_t sw = SW128((uint32_t)(row*128 + ch*16));
            *reinterpret_cast<uint4*>(sKh + sw) = srch[row*8 + ch];
            *reinterpret_cast<uint4*>(sKl + sw) = srcl[row*8 + ch];
        }
    }
    __syncthreads();

    uint32_t qh[4][4], ql[4][4];
    int a_row = lid & 15, a_cb = (lid >> 4) * 16;
#pragma unroll
    for (int ks = 0; ks < 4; ks++) {
        uint32_t off = SW128((uint32_t)((wid*16 + a_row)*128 + ks*32 + a_cb));
        LDSM_X4(qh[ks][0], qh[ks][1], qh[ks][2], qh[ks][3], skh + off);
        LDSM_X4(ql[ks][0], ql[ks][1], ql[ks][2], ql[ks][3], skl + off);
    }
    __syncthreads();

    float o[8][4];
#pragma unroll
    for (int i = 0; i < 8; i++)
#pragma unroll
        for (int j = 0; j < 4; j++) o[i][j] = 0.f;
    float m0 = -INFINITY, m1 = -INFINITY, l0 = 0.f, l1 = 0.f;

    int b_row = (lid & 7) + ((lid >> 4) << 3);
    int b_cb  = ((lid >> 3) & 1) * 16;
    int v_row = (lid & 7) + (((lid >> 3) & 1) << 3);
    int v_cb  = (lid >> 4) << 4;

    for (int kt = 0; kt <= qt; kt++) {
        {
            const uint4* kh4 = reinterpret_cast<const uint4*>(g_kh + hoff + (size_t)kt*64*HD);
            const uint4* kl4 = reinterpret_cast<const uint4*>(g_kl + hoff + (size_t)kt*64*HD);
            const uint4* vh4 = reinterpret_cast<const uint4*>(g_vh + hoff + (size_t)kt*64*HD);
            const uint4* vl4 = reinterpret_cast<const uint4*>(g_vl + hoff + (size_t)kt*64*HD);
#pragma unroll
            for (int i = 0; i < 4; i++) {
                int idx = tid + i*128;
                int row = idx >> 3, ch = idx & 7;
                uint32_t sw = SW128((uint32_t)(row*128 + ch*16));
                int si = row*8 + ch;
                *reinterpret_cast<uint4*>(sKh + sw) = kh4[si];
                *reinterpret_cast<uint4*>(sKl + sw) = kl4[si];
                *reinterpret_cast<uint4*>(sVh + sw) = vh4[si];
                *reinterpret_cast<uint4*>(sVl + sw) = vl4[si];
            }
        }
        __syncthreads();

        // ---- S = Q K^T (3 passes) ----
        float s[8][4];
#pragma unroll
        for (int i = 0; i < 8; i++)
#pragma unroll
            for (int j = 0; j < 4; j++) s[i][j] = 0.f;

#pragma unroll
        for (int ks = 0; ks < 4; ks++) {
#pragma unroll
            for (int nn = 0; nn < 4; nn++) {
                uint32_t off = SW128((uint32_t)((nn*16 + b_row)*128 + ks*32 + b_cb));
                uint32_t k0, k1, k2, k3, c0, c1, c2, c3;
                LDSM_X4(k0, k1, k2, k3, skh + off);
                LDSM_X4(c0, c1, c2, c3, skl + off);
                MMA_BF16(s[nn*2],   qh[ks][0], qh[ks][1], qh[ks][2], qh[ks][3], k0, k1);
                MMA_BF16(s[nn*2+1], qh[ks][0], qh[ks][1], qh[ks][2], qh[ks][3], k2, k3);
                MMA_BF16(s[nn*2],   qh[ks][0], qh[ks][1], qh[ks][2], qh[ks][3], c0, c1);
                MMA_BF16(s[nn*2+1], qh[ks][0], qh[ks][1], qh[ks][2], qh[ks][3], c2, c3);
                MMA_BF16(s[nn*2],   ql[ks][0], ql[ks][1], ql[ks][2], ql[ks][3], k0, k1);
                MMA_BF16(s[nn*2+1], ql[ks][0], ql[ks][1], ql[ks][2], ql[ks][3], k2, k3);
            }
        }

        // ---- scale + causal mask ----
        if (kt == qt) {
#pragma unroll
            for (int ni = 0; ni < 8; ni++)
#pragma unroll
                for (int j = 0; j < 4; j++) {
                    int ct = ni*8 + 2*t4 + (j & 1);
                    int rt = wid*16 + g + ((j >> 1) << 3);
                    s[ni][j] = (ct <= rt) ? s[ni][j] * 0.125f : -INFINITY;
                }
        } else {
#pragma unroll
            for (int ni = 0; ni < 8; ni++)
#pragma unroll
                for (int j = 0; j < 4; j++) s[ni][j] *= 0.125f;
        }

        // ---- online softmax ----
        float mt0 = m0, mt1 = m1;
#pragma unroll
        for (int ni = 0; ni < 8; ni++) {
            mt0 = fmaxf(mt0, fmaxf(s[ni][0], s[ni][1]));
            mt1 = fmaxf(mt1, fmaxf(s[ni][2], s[ni][3]));
        }
        mt0 = fmaxf(mt0, __shfl_xor_sync(0xffffffffu, mt0, 1));
        mt0 = fmaxf(mt0, __shfl_xor_sync(0xffffffffu, mt0, 2));
        mt1 = fmaxf(mt1, __shfl_xor_sync(0xffffffffu, mt1, 1));
        mt1 = fmaxf(mt1, __shfl_xor_sync(0xffffffffu, mt1, 2));

        float alpha0 = __expf(m0 - mt0);
        float alpha1 = __expf(m1 - mt1);
        m0 = mt0; m1 = mt1;

        float ps0 = 0.f, ps1 = 0.f;
#pragma unroll
        for (int ni = 0; ni < 8; ni++) {
            s[ni][0] = __expf(s[ni][0] - m0);
            s[ni][1] = __expf(s[ni][1] - m0);
            s[ni][2] = __expf(s[ni][2] - m1);
            s[ni][3] = __expf(s[ni][3] - m1);
            ps0 += s[ni][0] + s[ni][1];
            ps1 += s[ni][2] + s[ni][3];
        }
        ps0 += __shfl_xor_sync(0xffffffffu, ps0, 1);
        ps0 += __shfl_xor_sync(0xffffffffu, ps0, 2);
        ps1 += __shfl_xor_sync(0xffffffffu, ps1, 1);
        ps1 += __shfl_xor_sync(0xffffffffu, ps1, 2);
        l0 = l0 * alpha0 + ps0;
        l1 = l1 * alpha1 + ps1;

#pragma unroll
        for (int dt = 0; dt < 8; dt++) {
            o[dt][0] *= alpha0; o[dt][1] *= alpha0;
            o[dt][2] *= alpha1; o[dt][3] *= alpha1;
        }

        // ---- P fragments, split hi/lo in regs ----
        uint32_t ph[4][4], pl[4][4];
#pragma unroll
        for (int kc = 0; kc < 4; kc++) {
            float x0 = s[2*kc][0],   x1 = s[2*kc][1],   x2 = s[2*kc][2],   x3 = s[2*kc][3];
            float y0 = s[2*kc+1][0], y1 = s[2*kc+1][1], y2 = s[2*kc+1][2], y3 = s[2*kc+1][3];
            ph[kc][0] = pack2_hi(x0, x1);
            ph[kc][1] = pack2_hi(x2, x3);
            ph[kc][2] = pack2_hi(y0, y1);
            ph[kc][3] = pack2_hi(y2, y3);
            pl[kc][0] = pack2_rn(x0 - hi_trunc(x0), x1 - hi_trunc(x1));
            pl[kc][1] = pack2_rn(x2 - hi_trunc(x2), x3 - hi_trunc(x3));
            pl[kc][2] = pack2_rn(y0 - hi_trunc(y0), y1 - hi_trunc(y1));
            pl[kc][3] = pack2_rn(y2 - hi_trunc(y2), y3 - hi_trunc(y3));
        }

        // ---- O += P V (3 passes, V via ldmatrix.trans) ----
#pragma unroll
        for (int kc = 0; kc < 4; kc++) {
#pragma unroll
            for (int dn = 0; dn < 4; dn++) {
                uint32_t off = SW128((uint32_t)((kc*16 + v_row)*128 + dn*32 + v_cb));
                uint32_t vh0, vh1, vh2, vh3, vl0, vl1, vl2, vl3;
                LDSM_X4_T(vh0, vh1, vh2, vh3, svh + off);
                LDSM_X4_T(vl0, vl1, vl2, vl3, svl + off);
                MMA_BF16(o[dn*2],   ph[kc][0], ph[kc][1], ph[kc][2], ph[kc][3], vh0, vh1);
                MMA_BF16(o[dn*2+1], ph[kc][0], ph[kc][1], ph[kc][2], ph[kc][3], vh2, vh3);
                MMA_BF16(o[dn*2],   ph[kc][0], ph[kc][1], ph[kc][2], ph[kc][3], vl0, vl1);
                MMA_BF16(o[dn*2+1], ph[kc][0], ph[kc][1], ph[kc][2], ph[kc][3], vl2, vl3);
                MMA_BF16(o[dn*2],   pl[kc][0], pl[kc][1], pl[kc][2], pl[kc][3], vh0, vh1);
                MMA_BF16(o[dn*2+1], pl[kc][0], pl[kc][1], pl[kc][2], pl[kc][3], vh2, vh3);
            }
        }
        __syncthreads();
    }

    // ---- epilogue: normalize, write split bf16 into g_yh/g_yl ----
    float inv0 = 1.f / l0, inv1 = 1.f / l1;
    int b = bh >> 4, h = bh & 15;
    int row0 = q0 + wid*16 + g;
    int row1 = row0 + 8;
    size_t off0 = ((size_t)b*TT + row0)*CC + h*HD;
    size_t off1 = ((size_t)b*TT + row1)*CC + h*HD;
#pragma unroll
    for (int dt = 0; dt < 8; dt++) {
        int d = dt*8 + 2*t4;
        float w0x = o[dt][0]*inv0, w0y = o[dt][1]*inv0;
        float w1x = o[dt][2]*inv1, w1y = o[dt][3]*inv1;
        ((uint32_t*)g_yh)[(off0 + d) >> 1] = pack2_hi(w0x, w0y);
        ((uint32_t*)g_yl)[(off0 + d) >> 1] =
            pack2_rn(w0x - hi_trunc(w0x), w0y - hi_trunc(w0y));
        ((uint32_t*)g_yh)[(off1 + d) >> 1] = pack2_hi(w1x, w1y);
        ((uint32_t*)g_yl)[(off1 + d) >> 1] =
            pack2_rn(w1x - hi_trunc(w1x), w1y - hi_trunc(w1y));
    }
}

// ---------------------------------------------------------------------------
extern "C" void kernel_launch(void* const* d_in, const int* in_sizes, int n_in,
                              void* d_out, int out_size)
{
    const float* x      = (const float*)d_in[0];   // [B,T,C]
    const float* W_attn = (const float*)d_in[1];   // [3C,C]
    const float* b_attn = (const float*)d_in[2];   // [3C]
    const float* W_proj = (const float*)d_in[3];   // [C,C]
    const float* b_proj = (const float*)d_in[4];   // [C]
    float* out = (float*)d_out;                    // [B,T,C]

    cudaFuncSetAttribute(gemm_tc<1>, cudaFuncAttributeMaxDynamicSharedMemorySize, SM_TOTAL);
    cudaFuncSetAttribute(gemm_tc<2>, cudaFuncAttributeMaxDynamicSharedMemorySize, SM_TOTAL);

    // 0) one-time splits (x, W_attn, W_proj)
    {
        __nv_bfloat16 *xh, *xl, *wah, *wal, *wph, *wpl;
        cudaGetSymbolAddress((void**)&xh,  g_xh);
        cudaGetSymbolAddress((void**)&xl,  g_xl);
        cudaGetSymbolAddress((void**)&wah, g_wah);
        cudaGetSymbolAddress((void**)&wal, g_wal);
        cudaGetSymbolAddress((void**)&wph, g_wph);
        cudaGetSymbolAddress((void**)&wpl, g_wpl);
        int n4x = M_TOT*CC/4, n4a = N_QKV*CC/4, n4p = CC*CC/4;
        convert_split<<<(n4x+255)/256, 256>>>((const float4*)x,
            (uint32_t*)xh, (uint32_t*)xl, n4x);
        convert_split<<<(n4a+255)/256, 256>>>((const float4*)W_attn,
            (uint32_t*)wah, (uint32_t*)wal, n4a);
        convert_split<<<(n4p+255)/256, 256>>>((const float4*)W_proj,
            (uint32_t*)wph, (uint32_t*)wpl, n4p);
    }

    // 1) QKV projection (pipelined bf16-split GEMM) -> q/k/v hi/lo scatter
    gemm_tc<1><<<dim3(N_QKV/128, M_TOT/128), 256, SM_TOTAL>>>(b_attn, nullptr, CC, N_QKV);
    // 2) causal flash attention (tensor cores, split-bf16)
    attn_tc<<<dim3(TT/64, BB*HH), 128>>>();
    // 3) output projection (pipelined bf16-split GEMM)
    gemm_tc<2><<<dim3(CC/128, M_TOT/128), 256, SM_TOTAL>>>(b_proj, out, CC, CC);
}